// round 14
// baseline (speedup 1.0000x reference)
#include <cuda_runtime.h>
#include <cuda_fp16.h>
#include <math.h>
#include <stdint.h>

// ---------------- Static forest topology ----------------
#define TREES     50
#define DEPTH     10
#define PER_TREE  2047
#define NNODES    (TREES * PER_TREE)   // 102350
#define FEAT      512
#define HID       512
#define IOUD      1536
#define NLEAVES   (TREES * 1024)
#define NINTER    (TREES * 1023)       // 51150 interior nodes

// ---------------- Device scratch ----------------
__device__ __half g_Xiou16[(size_t)NNODES * IOUD];
__device__ __half g_Xf16  [(size_t)NNODES * HID];
__device__ __half g_iou16 [(size_t)(TREES * 512) * IOUD];
__device__ __half g_fg16  [(size_t)(TREES * 1024) * 1024];
__device__ float  g_bcat[2048];
__device__ __half g_feat16[(size_t)NNODES * FEAT];
__device__ __half g_h16   [(size_t)NNODES * HID];
__device__ __half g_W16   [(size_t)2048 * FEAT];        // [W_iou(1536) ; W_f(512)] rows
__device__ __half g_Uiou16[(size_t)IOUD * 1024];
__device__ __half g_Uf16  [(size_t)1024 * HID];

__device__ __forceinline__ float sigmoidf_(float x) { return 1.0f / (1.0f + expf(-x)); }

// ---------------- Common GEMM pieces ----------------
#define BK 32
#define A_STG 8192                     // 128 rows * 64B

__device__ __forceinline__ void mma16(float c[4], uint32_t a0, uint32_t a1, uint32_t a2,
                                      uint32_t a3, uint32_t b0, uint32_t b1) {
    asm volatile("mma.sync.aligned.m16n8k16.row.col.f32.f16.f16.f32 "
        "{%0,%1,%2,%3}, {%4,%5,%6,%7}, {%8,%9}, {%0,%1,%2,%3};"
        : "+f"(c[0]), "+f"(c[1]), "+f"(c[2]), "+f"(c[3])
        : "r"(a0), "r"(a1), "r"(a2), "r"(a3), "r"(b0), "r"(b1));
}
__device__ __forceinline__ void ldsm4(uint32_t& r0, uint32_t& r1, uint32_t& r2, uint32_t& r3,
                                      uint32_t a) {
    asm volatile("ldmatrix.sync.aligned.m8n8.x4.shared.b16 {%0,%1,%2,%3}, [%4];"
        : "=r"(r0), "=r"(r1), "=r"(r2), "=r"(r3) : "r"(a));
}

// ---- A-row gather per MODE (see level/proj kernels) ----
template <int MODE>
__device__ __forceinline__ const __half* a_row(const __half* __restrict__ A,
                                               int gm, int K, int shift, int off_child)
{
    if (MODE == 0) return A + (size_t)gm * K;
    if (MODE == 1) {
        int t = gm >> shift, i = gm & ((1 << shift) - 1);
        return A + (size_t)(t * PER_TREE + off_child + 2 * i) * HID;
    }
    if (MODE == 2) {
        int t = gm >> shift, j = gm & ((1 << shift) - 1);
        return A + (size_t)(t * PER_TREE + off_child + j) * HID;
    }
    unsigned t = (unsigned)gm / 1023u;
    unsigned i = (unsigned)gm - t * 1023u;
    return A + (size_t)(t * 2047u + 1024u + i) * (size_t)K;
}

// =====================================================================
// LEVEL GEMM (R12 config): CTA 128x128, 256 thr, 8 warps (2M x 4N), warp 64x32,
// 3-stage static 48KB smem, 2 CTAs/SM.
// =====================================================================
#define BM 128
#define BN 128
#define STG   16384
#define STAGES 3

template <int MODE>
__device__ __forceinline__ void stage_cp(uint32_t sA, uint32_t sB,
    const __half* __restrict__ A, const __half* __restrict__ B,
    int M, int K, int bm, int bn, int k0, int shift, int off_child, int tid)
{
#pragma unroll
    for (int q = 0; q < 2; q++) {      // A: 512 chunks, 2 per thread
        int id = q * 256 + tid;
        int r = id >> 2, cch = id & 3;
        int gm = bm + r;
        unsigned sz = 16u;
        if (gm >= M) { sz = 0u; gm = M - 1; }
        const __half* rowA = a_row<MODE>(A, gm, K, shift, off_child);
        uint32_t dst = sA + r * 64 + ((cch ^ ((r >> 1) & 3)) << 4);
        asm volatile("cp.async.cg.shared.global [%0], [%1], 16, %2;"
            :: "r"(dst), "l"(rowA + k0 + cch * 8), "r"(sz) : "memory");
    }
#pragma unroll
    for (int q = 0; q < 2; q++) {      // B: 512 chunks, 2 per thread
        int id = q * 256 + tid;
        int r = id >> 2, cch = id & 3;
        uint32_t dst = sB + r * 64 + ((cch ^ ((r >> 1) & 3)) << 4);
        asm volatile("cp.async.cg.shared.global [%0], [%1], 16;"
            :: "r"(dst), "l"(B + (size_t)(bn + r) * K + k0 + cch * 8) : "memory");
    }
}

__device__ __forceinline__ void load_frags(uint32_t (&af)[4][4], uint32_t (&bf)[4][2],
    uint32_t sAo, uint32_t sBo, int wm, int wn, int lane, int kc)
{
    const int arow = lane & 15;
    const int ca = kc * 2 + ((lane >> 4) & 1);
#pragma unroll
    for (int mt = 0; mt < 4; mt++) {
        int r = wm + mt * 16 + arow;
        ldsm4(af[mt][0], af[mt][1], af[mt][2], af[mt][3],
              sAo + r * 64 + ((ca ^ ((r >> 1) & 3)) << 4));
    }
    const int brow = (lane & 7) + ((lane >> 4) & 1) * 8;
    const int cb = kc * 2 + ((lane >> 3) & 1);
#pragma unroll
    for (int ng = 0; ng < 2; ng++) {
        int r = wn + ng * 16 + brow;
        uint32_t r0, r1, r2, r3;
        ldsm4(r0, r1, r2, r3, sBo + r * 64 + ((cb ^ ((r >> 1) & 3)) << 4));
        bf[ng * 2][0] = r0;     bf[ng * 2][1] = r1;
        bf[ng * 2 + 1][0] = r2; bf[ng * 2 + 1][1] = r3;
    }
}
__device__ __forceinline__ void mma_all(float (&acc)[4][4][4],
    const uint32_t (&af)[4][4], const uint32_t (&bf)[4][2])
{
#pragma unroll
    for (int mt = 0; mt < 4; mt++)
#pragma unroll
        for (int nt = 0; nt < 4; nt++)
            mma16(acc[mt][nt], af[mt][0], af[mt][1], af[mt][2], af[mt][3],
                  bf[nt][0], bf[nt][1]);
}

// MODE 1: C[gm] direct, +AddH = g_Xiou16[parent*IOUD + gn]
// MODE 2: C[gm] direct, no addend
template <int MODE>
__device__ __forceinline__ void gemm_body(
    const __half* __restrict__ A, const __half* __restrict__ B,
    __half* __restrict__ C, const __half* __restrict__ AddH,
    int M, int Nd, int K, int shift, int off_parent, int off_child,
    int bm, int bn, uint32_t sb)
{
    const int tid = threadIdx.x, lane = tid & 31, wid = tid >> 5;
    const int wm = (wid & 1) * 64, wn = (wid >> 1) * 32;
    const int g = lane >> 2, tig = lane & 3;

    float acc[4][4][4];
#pragma unroll
    for (int mt = 0; mt < 4; mt++)
#pragma unroll
        for (int nt = 0; nt < 4; nt++)
#pragma unroll
            for (int r = 0; r < 4; r++) acc[mt][nt][r] = 0.f;

    const int NC = K >> 5;
    stage_cp<MODE>(sb, sb + A_STG, A, B, M, K, bm, bn, 0, shift, off_child, tid);
    asm volatile("cp.async.commit_group;" ::: "memory");
    stage_cp<MODE>(sb + STG, sb + STG + A_STG, A, B, M, K, bm, bn, BK, shift, off_child, tid);
    asm volatile("cp.async.commit_group;" ::: "memory");
    asm volatile("cp.async.wait_group 1;" ::: "memory");
    __syncthreads();

    for (int s = 0; s < NC; s++) {
        const uint32_t sAo = sb + (s % 3) * STG;
        const uint32_t sBo = sAo + A_STG;
        uint32_t af[4][4], bf[4][2];

        load_frags(af, bf, sAo, sBo, wm, wn, lane, 0);
        mma_all(acc, af, bf);

        if (s + 2 < NC) {
            const uint32_t so = sb + ((s + 2) % 3) * STG;
            stage_cp<MODE>(so, so + A_STG, A, B, M, K, bm, bn, (s + 2) * BK,
                           shift, off_child, tid);
            asm volatile("cp.async.commit_group;" ::: "memory");
        }

        load_frags(af, bf, sAo, sBo, wm, wn, lane, 1);
        mma_all(acc, af, bf);

        if (s + 1 < NC) {
            if (s + 2 < NC) { asm volatile("cp.async.wait_group 1;" ::: "memory"); }
            else            { asm volatile("cp.async.wait_group 0;" ::: "memory"); }
            __syncthreads();
        }
    }

#pragma unroll
    for (int mt = 0; mt < 4; mt++) {
#pragma unroll
        for (int half_ = 0; half_ < 2; half_++) {
            int gm = bm + wm + mt * 16 + g + half_ * 8;
            if (gm >= M) continue;
            size_t crow = (size_t)gm * Nd, addb = 0;
            if (MODE == 1) {
                int t = gm >> shift, ii = gm & ((1 << shift) - 1);
                addb = (size_t)(t * PER_TREE + off_parent + ii) * IOUD;
            }
#pragma unroll
            for (int nt = 0; nt < 4; nt++) {
                int gn = bn + wn + nt * 8 + 2 * tig;
                float vx = acc[mt][nt][half_ * 2 + 0];
                float vy = acc[mt][nt][half_ * 2 + 1];
                if (MODE == 1) {
                    float2 a = __half22float2(*reinterpret_cast<const __half2*>(AddH + addb + gn));
                    vx += a.x; vy += a.y;
                }
                *reinterpret_cast<__half2*>(C + crow + gn) = __floats2half2_rn(vx, vy);
            }
        }
    }
}

// Fused per-level kernel: iou GEMM + fg GEMM in one launch.
__global__ void __launch_bounds__(256, 2) gemm_level_k(
    const __half* __restrict__ h16,
    const __half* __restrict__ Uiou, const __half* __restrict__ Uf,
    __half* __restrict__ ioub, __half* __restrict__ fgb,
    const __half* __restrict__ Xiou,
    int P, int shift, int off_p, int off_c, int Biou)
{
    __shared__ __align__(16) unsigned char smem[STAGES * STG];
    const uint32_t sb = (uint32_t)__cvta_generic_to_shared(smem);
    int bid = blockIdx.x;
    if (bid < Biou) {
        int bxn = bid % 12, bym = bid / 12;
        gemm_body<1>(h16, Uiou, ioub, Xiou,
                     P, IOUD, 1024, shift, off_p, off_c, bym * BM, bxn * BN, sb);
    } else {
        int b2 = bid - Biou;
        int bxn = b2 % 8, bym = b2 / 8;
        gemm_body<2>(h16, Uf, fgb, nullptr,
                     2 * P, 1024, 512, shift + 1, 0, off_c, bym * BM, bxn * BN, sb);
    }
}

// =====================================================================
// PROJECTION GEMM: CTA 128x256, 256 thr, 8 warps (2M x 4N), warp 64x64,
// 3-stage dynamic 72KB smem, 1 CTA/SM. MODE 0 (direct+bias), MODE 3 (interior scatter+bias).
// =====================================================================
#define BNP 256
#define B_STGP 16384
#define STGP (A_STG + B_STGP)          // 24576
#define SMEM_PROJ (3 * STGP)           // 73728

template <int MODE>
__device__ __forceinline__ void stage_cp_p(uint32_t sA, uint32_t sB,
    const __half* __restrict__ A, const __half* __restrict__ B,
    int M, int K, int bm, int bn, int k0, int tid)
{
#pragma unroll
    for (int q = 0; q < 2; q++) {      // A: 512 chunks, 2 per thread
        int id = q * 256 + tid;
        int r = id >> 2, cch = id & 3;
        int gm = bm + r;
        unsigned sz = 16u;
        if (gm >= M) { sz = 0u; gm = M - 1; }
        const __half* rowA = a_row<MODE>(A, gm, K, 0, 0);
        uint32_t dst = sA + r * 64 + ((cch ^ ((r >> 1) & 3)) << 4);
        asm volatile("cp.async.cg.shared.global [%0], [%1], 16, %2;"
            :: "r"(dst), "l"(rowA + k0 + cch * 8), "r"(sz) : "memory");
    }
#pragma unroll
    for (int q = 0; q < 4; q++) {      // B: 1024 chunks, 4 per thread
        int id = q * 256 + tid;
        int r = id >> 2, cch = id & 3;
        uint32_t dst = sB + r * 64 + ((cch ^ ((r >> 1) & 3)) << 4);
        asm volatile("cp.async.cg.shared.global [%0], [%1], 16;"
            :: "r"(dst), "l"(B + (size_t)(bn + r) * K + k0 + cch * 8) : "memory");
    }
}

__device__ __forceinline__ void load_frags_p(uint32_t (&af)[4][4], uint32_t (&bf)[8][2],
    uint32_t sAo, uint32_t sBo, int wm, int wn, int lane, int kc)
{
    const int arow = lane & 15;
    const int ca = kc * 2 + ((lane >> 4) & 1);
#pragma unroll
    for (int mt = 0; mt < 4; mt++) {
        int r = wm + mt * 16 + arow;
        ldsm4(af[mt][0], af[mt][1], af[mt][2], af[mt][3],
              sAo + r * 64 + ((ca ^ ((r >> 1) & 3)) << 4));
    }
    const int brow = (lane & 7) + ((lane >> 4) & 1) * 8;
    const int cb = kc * 2 + ((lane >> 3) & 1);
#pragma unroll
    for (int ng = 0; ng < 4; ng++) {
        int r = wn + ng * 16 + brow;
        uint32_t r0, r1, r2, r3;
        ldsm4(r0, r1, r2, r3, sBo + r * 64 + ((cb ^ ((r >> 1) & 3)) << 4));
        bf[ng * 2][0] = r0;     bf[ng * 2][1] = r1;
        bf[ng * 2 + 1][0] = r2; bf[ng * 2 + 1][1] = r3;
    }
}
__device__ __forceinline__ void mma_all_p(float (&acc)[4][8][4],
    const uint32_t (&af)[4][4], const uint32_t (&bf)[8][2])
{
#pragma unroll
    for (int mt = 0; mt < 4; mt++)
#pragma unroll
        for (int nt = 0; nt < 8; nt++)
            mma16(acc[mt][nt], af[mt][0], af[mt][1], af[mt][2], af[mt][3],
                  bf[nt][0], bf[nt][1]);
}

template <int MODE>
__global__ void __launch_bounds__(256, 1) gemm_proj_k(
    const __half* __restrict__ A, const __half* __restrict__ B,
    __half* __restrict__ C, const float* __restrict__ AddF,
    int M, int Nd, int K)
{
    extern __shared__ __align__(16) unsigned char smem[];
    const uint32_t sb = (uint32_t)__cvta_generic_to_shared(smem);
    const int tid = threadIdx.x, lane = tid & 31, wid = tid >> 5;
    const int wm = (wid & 1) * 64, wn = (wid >> 1) * 64;
    const int g = lane >> 2, tig = lane & 3;
    const int bm = blockIdx.y * BM, bn = blockIdx.x * BNP;

    float acc[4][8][4];
#pragma unroll
    for (int mt = 0; mt < 4; mt++)
#pragma unroll
        for (int nt = 0; nt < 8; nt++)
#pragma unroll
            for (int r = 0; r < 4; r++) acc[mt][nt][r] = 0.f;

    const int NC = K >> 5;
    stage_cp_p<MODE>(sb, sb + A_STG, A, B, M, K, bm, bn, 0, tid);
    asm volatile("cp.async.commit_group;" ::: "memory");
    stage_cp_p<MODE>(sb + STGP, sb + STGP + A_STG, A, B, M, K, bm, bn, BK, tid);
    asm volatile("cp.async.commit_group;" ::: "memory");
    asm volatile("cp.async.wait_group 1;" ::: "memory");
    __syncthreads();

    for (int s = 0; s < NC; s++) {
        const uint32_t sAo = sb + (s % 3) * STGP;
        const uint32_t sBo = sAo + A_STG;
        uint32_t af[4][4], bf[8][2];

        load_frags_p(af, bf, sAo, sBo, wm, wn, lane, 0);
        mma_all_p(acc, af, bf);

        if (s + 2 < NC) {
            const uint32_t so = sb + ((s + 2) % 3) * STGP;
            stage_cp_p<MODE>(so, so + A_STG, A, B, M, K, bm, bn, (s + 2) * BK, tid);
            asm volatile("cp.async.commit_group;" ::: "memory");
        }

        load_frags_p(af, bf, sAo, sBo, wm, wn, lane, 1);
        mma_all_p(acc, af, bf);

        if (s + 1 < NC) {
            if (s + 2 < NC) { asm volatile("cp.async.wait_group 1;" ::: "memory"); }
            else            { asm volatile("cp.async.wait_group 0;" ::: "memory"); }
            __syncthreads();
        }
    }

#pragma unroll
    for (int mt = 0; mt < 4; mt++) {
#pragma unroll
        for (int half_ = 0; half_ < 2; half_++) {
            int gm = bm + wm + mt * 16 + g + half_ * 8;
            if (gm >= M) continue;
            size_t crow;
            if (MODE == 3) {
                unsigned t = (unsigned)gm / 1023u;
                unsigned i = (unsigned)gm - t * 1023u;
                crow = (size_t)(t * 2047u + 1024u + i) * Nd;
            } else {
                crow = (size_t)gm * Nd;
            }
#pragma unroll
            for (int nt = 0; nt < 8; nt++) {
                int gn = bn + wn + nt * 8 + 2 * tig;
                float vx = acc[mt][nt][half_ * 2 + 0] + AddF[gn];
                float vy = acc[mt][nt][half_ * 2 + 1] + AddF[gn + 1];
                *reinterpret_cast<__half2*>(C + crow + gn) = __floats2half2_rn(vx, vy);
            }
        }
    }
}

// ---------------- Conversion / packing ----------------
__global__ void f2h_kernel(const float* __restrict__ s, __half* __restrict__ d, int n2) {
    int i = blockIdx.x * blockDim.x + threadIdx.x;
    if (i >= n2) return;
    float2 v = reinterpret_cast<const float2*>(s)[i];
    reinterpret_cast<__half2*>(d)[i] = __floats2half2_rn(v.x, v.y);
}
__global__ void pack_W16(const float* __restrict__ Wiou, const float* __restrict__ Wf,
                         const float* __restrict__ biou, const float* __restrict__ bfp,
                         __half* __restrict__ W, float* __restrict__ bc) {
    int idx = blockIdx.x * blockDim.x + threadIdx.x;
    if (idx >= 2048 * FEAT) return;
    int j = idx >> 9, k = idx & 511;
    float v = (j < IOUD) ? Wiou[j * FEAT + k] : Wf[(j - IOUD) * FEAT + k];
    W[idx] = __float2half(v);
    if (k == 0) bc[j] = (j < IOUD) ? biou[j] : bfp[j - IOUD];
}
__global__ void pack_Uiou16(const float* __restrict__ Ul, const float* __restrict__ Ur,
                            __half* __restrict__ U) {
    int idx = blockIdx.x * blockDim.x + threadIdx.x;
    if (idx >= IOUD * 1024) return;
    int j = idx >> 10, k = idx & 1023;
    U[idx] = __float2half((k < 512) ? Ul[j * 512 + k] : Ur[j * 512 + (k - 512)]);
}
__global__ void pack_Uf16(const float* __restrict__ Ul, const float* __restrict__ Ur,
                          __half* __restrict__ U) {
    int idx = blockIdx.x * blockDim.x + threadIdx.x;
    if (idx >= 1024 * HID) return;
    U[idx] = __float2half((idx < 512 * 512) ? Ul[idx] : Ur[idx - 512 * 512]);
}

// ---------------- Leaf elementwise (2 elems/thread, half2) ----------------
__global__ void leaf_kernel(const __half* __restrict__ Xiou,
                            float* __restrict__ h, float* __restrict__ c,
                            __half* __restrict__ h16, int total)
{
    int idx = blockIdx.x * blockDim.x + threadIdx.x;
    if (idx >= total) return;
    int leaf = idx >> 8, p = idx & 255;
    int hid = p * 2;
    int t = leaf >> 10, i = leaf & 1023;
    int node = t * PER_TREE + i;
    size_t base = (size_t)node * IOUD;
    float2 iv = __half22float2(*reinterpret_cast<const __half2*>(Xiou + base + hid));
    float2 ov = __half22float2(*reinterpret_cast<const __half2*>(Xiou + base + 512 + hid));
    float2 uv = __half22float2(*reinterpret_cast<const __half2*>(Xiou + base + 1024 + hid));
    float cnx = sigmoidf_(iv.x) * tanhf(uv.x);
    float cny = sigmoidf_(iv.y) * tanhf(uv.y);
    float hnx = sigmoidf_(ov.x) * tanhf(cnx);
    float hny = sigmoidf_(ov.y) * tanhf(cny);
    size_t ob = (size_t)node * HID + hid;
    *reinterpret_cast<float2*>(c + ob) = make_float2(cnx, cny);
    *reinterpret_cast<float2*>(h + ob) = make_float2(hnx, hny);
    *reinterpret_cast<__half2*>(h16 + ob) = __floats2half2_rn(hnx, hny);
}

// ---------------- Per-level combine (2 elems/thread) ----------------
__global__ void combine_kernel(const __half* __restrict__ iou, const __half* __restrict__ fg,
                               const __half* __restrict__ Xf,
                               float* __restrict__ h, float* __restrict__ c,
                               __half* __restrict__ h16,
                               int P, int shift, int off_parent, int off_child)
{
    int idx = blockIdx.x * blockDim.x + threadIdx.x;
    if (idx >= P * 256) return;
    int pid = idx >> 8, p = idx & 255;
    int hid = p * 2;
    int t = pid >> shift, i = pid & ((1 << shift) - 1);
    int node = t * PER_TREE + off_parent + i;
    int cl   = t * PER_TREE + off_child + 2 * i;

    size_t ib = (size_t)pid * IOUD;
    float2 iv = __half22float2(*reinterpret_cast<const __half2*>(iou + ib + hid));
    float2 ov = __half22float2(*reinterpret_cast<const __half2*>(iou + ib + 512 + hid));
    float2 uv = __half22float2(*reinterpret_cast<const __half2*>(iou + ib + 1024 + hid));
    float2 xf = __half22float2(*reinterpret_cast<const __half2*>(Xf + (size_t)node * HID + hid));

    size_t fL = (size_t)(2 * pid) * 1024;
    size_t fR = fL + 1024;
    float2 glL = __half22float2(*reinterpret_cast<const __half2*>(fg + fL + hid));
    float2 grL = __half22float2(*reinterpret_cast<const __half2*>(fg + fL + 512 + hid));
    float2 glR = __half22float2(*reinterpret_cast<const __half2*>(fg + fR + hid));
    float2 grR = __half22float2(*reinterpret_cast<const __half2*>(fg + fR + 512 + hid));
    float2 ccL = *reinterpret_cast<const float2*>(c + (size_t)cl * HID + hid);
    float2 ccR = *reinterpret_cast<const float2*>(c + (size_t)(cl + 1) * HID + hid);

    float fcx = (sigmoidf_(xf.x + glL.x) + sigmoidf_(xf.x + grL.x)) * ccL.x
              + (sigmoidf_(xf.x + glR.x) + sigmoidf_(xf.x + grR.x)) * ccR.x;
    float fcy = (sigmoidf_(xf.y + glL.y) + sigmoidf_(xf.y + grL.y)) * ccL.y
              + (sigmoidf_(xf.y + glR.y) + sigmoidf_(xf.y + grR.y)) * ccR.y;

    float cnx = sigmoidf_(iv.x) * tanhf(uv.x) + fcx;
    float cny = sigmoidf_(iv.y) * tanhf(uv.y) + fcy;
    float hnx = sigmoidf_(ov.x) * tanhf(cnx);
    float hny = sigmoidf_(ov.y) * tanhf(cny);
    size_t ob = (size_t)node * HID + hid;
    *reinterpret_cast<float2*>(c + ob) = make_float2(cnx, cny);
    *reinterpret_cast<float2*>(h + ob) = make_float2(hnx, hny);
    *reinterpret_cast<__half2*>(h16 + ob) = __floats2half2_rn(hnx, hny);
}

// ---------------- Launch ----------------
extern "C" void kernel_launch(void* const* d_in, const int* in_sizes, int n_in,
                              void* d_out, int out_size)
{
    const float* features = (const float*)d_in[0];
    const float* W_iou_w = (const float*)d_in[4];
    const float* W_iou_b = (const float*)d_in[5];
    const float* U_iou_l = (const float*)d_in[6];
    const float* U_iou_r = (const float*)d_in[7];
    const float* W_f_w   = (const float*)d_in[8];
    const float* W_f_b   = (const float*)d_in[9];
    const float* U_f_l   = (const float*)d_in[10];
    const float* U_f_r   = (const float*)d_in[11];

    float* h = (float*)d_out;
    float* c = h + (size_t)NNODES * HID;

    float *bcat;
    __half *xiou16, *xf16, *ioub, *fgb, *feat16, *h16, *w16, *uiou16, *uf16;
    cudaGetSymbolAddress((void**)&xiou16, g_Xiou16);
    cudaGetSymbolAddress((void**)&xf16,   g_Xf16);
    cudaGetSymbolAddress((void**)&ioub,   g_iou16);
    cudaGetSymbolAddress((void**)&fgb,    g_fg16);
    cudaGetSymbolAddress((void**)&bcat,   g_bcat);
    cudaGetSymbolAddress((void**)&feat16, g_feat16);
    cudaGetSymbolAddress((void**)&h16,    g_h16);
    cudaGetSymbolAddress((void**)&w16,    g_W16);
    cudaGetSymbolAddress((void**)&uiou16, g_Uiou16);
    cudaGetSymbolAddress((void**)&uf16,   g_Uf16);

    cudaFuncSetAttribute(gemm_proj_k<0>, cudaFuncAttributeMaxDynamicSharedMemorySize, SMEM_PROJ);
    cudaFuncSetAttribute(gemm_proj_k<3>, cudaFuncAttributeMaxDynamicSharedMemorySize, SMEM_PROJ);

    // One-time conversions/packing (fp32 -> fp16)
    {
        int n2 = NNODES * FEAT / 2;
        f2h_kernel<<<(n2 + 255) / 256, 256>>>(features, feat16, n2);
    }
    pack_W16   <<<(2048 * FEAT + 255) / 256, 256>>>(W_iou_w, W_f_w, W_iou_b, W_f_b, w16, bcat);
    pack_Uiou16<<<(IOUD * 1024 + 255) / 256, 256>>>(U_iou_l, U_iou_r, uiou16);
    pack_Uf16  <<<(1024 * HID + 255) / 256, 256>>>(U_f_l, U_f_r, uf16);

    // Projection 1: X_iou = features @ W_iou^T + b_iou  (ALL nodes, Nd=1536, BN=256)
    {
        dim3 grid(IOUD / BNP, (NNODES + BM - 1) / BM);
        gemm_proj_k<0><<<grid, 256, SMEM_PROJ>>>(feat16, w16, xiou16, bcat,
                                                 NNODES, IOUD, FEAT);
    }
    // Projection 2: X_f = features @ W_f^T + b_f  (INTERIOR nodes only, Nd=512, BN=256)
    {
        dim3 grid(HID / BNP, (NINTER + BM - 1) / BM);
        gemm_proj_k<3><<<grid, 256, SMEM_PROJ>>>(feat16, w16 + (size_t)IOUD * FEAT, xf16,
                                                 bcat + IOUD, NINTER, HID, FEAT);
    }

    leaf_kernel<<<(NLEAVES * 256 + 255) / 256, 256>>>(xiou16, h, c, h16, NLEAVES * 256);

    for (int l = 1; l <= DEPTH; l++) {
        int n_l    = 1024 >> l;
        int P      = TREES * n_l;
        int shiftP = 10 - l;
        int off_p  = 2048 - (2048 >> l);
        int off_c  = 2048 - (2048 >> (l - 1));

        int Biou = 12 * ((P + BM - 1) / BM);
        int Bfg  = 8 * ((2 * P + BM - 1) / BM);
        gemm_level_k<<<Biou + Bfg, 256>>>(h16, uiou16, uf16, ioub, fgb, xiou16,
                                          P, shiftP, off_p, off_c, Biou);

        combine_kernel<<<(P * 256 + 255) / 256, 256>>>(ioub, fgb, xf16, h, c, h16,
                                                       P, shiftP, off_p, off_c);
    }
}

// round 15
// speedup vs baseline: 1.0397x; 1.0397x over previous
#include <cuda_runtime.h>
#include <cuda_fp16.h>
#include <math.h>
#include <stdint.h>

// ---------------- Static forest topology ----------------
#define TREES     50
#define DEPTH     10
#define PER_TREE  2047
#define NNODES    (TREES * PER_TREE)   // 102350
#define FEAT      512
#define HID       512
#define IOUD      1536
#define NLEAVES   (TREES * 1024)
#define NINTER    (TREES * 1023)       // 51150 interior nodes

// ---------------- Device scratch ----------------
__device__ __half g_Xiou16[(size_t)NNODES * IOUD];      // W_iou proj, all nodes
__device__ __half g_Xf16  [(size_t)NNODES * HID];       // W_f proj, interior rows only
__device__ __half g_iou16 [(size_t)(TREES * 512) * IOUD];
__device__ __half g_fg16  [(size_t)(TREES * 1024) * 1024];
__device__ float  g_bcat[2048];
__device__ __half g_feat16[(size_t)NNODES * FEAT];
__device__ __half g_h16   [(size_t)NNODES * HID];
__device__ __half g_W16   [(size_t)2048 * FEAT];        // [W_iou(1536) ; W_f(512)] rows
__device__ __half g_Uiou16[(size_t)IOUD * 1024];
__device__ __half g_Uf16  [(size_t)1024 * HID];

__device__ __forceinline__ float sigmoidf_(float x) { return 1.0f / (1.0f + expf(-x)); }

// ---------------- GEMM config (R12 proven optimum) ----------------
// CTA 128x128, BK=32 halves, 256 threads = 8 warps (2M x 4N), warp tile 64x32.
// 3-stage cp.async, 48KB static smem -> 2 CTAs/SM; <=128 regs via launch_bounds(256,2).
#define BM 128
#define BN 128
#define BK 32
#define A_STG 8192
#define B_STG 8192
#define STG   16384
#define STAGES 3                       // 49152 bytes static

__device__ __forceinline__ void mma16(float c[4], uint32_t a0, uint32_t a1, uint32_t a2,
                                      uint32_t a3, uint32_t b0, uint32_t b1) {
    asm volatile("mma.sync.aligned.m16n8k16.row.col.f32.f16.f16.f32 "
        "{%0,%1,%2,%3}, {%4,%5,%6,%7}, {%8,%9}, {%0,%1,%2,%3};"
        : "+f"(c[0]), "+f"(c[1]), "+f"(c[2]), "+f"(c[3])
        : "r"(a0), "r"(a1), "r"(a2), "r"(a3), "r"(b0), "r"(b1));
}
__device__ __forceinline__ void ldsm4(uint32_t& r0, uint32_t& r1, uint32_t& r2, uint32_t& r3,
                                      uint32_t a) {
    asm volatile("ldmatrix.sync.aligned.m8n8.x4.shared.b16 {%0,%1,%2,%3}, [%4];"
        : "=r"(r0), "=r"(r1), "=r"(r2), "=r"(r3) : "r"(a));
}

// ---- A-row gather per MODE:
// MODE 0: direct (lda=K)
// MODE 1: row m -> h16 of LEFT child (1024 contiguous halves span L+R child)
// MODE 2: row m -> h16 of child node (512 halves)
// MODE 3: row m -> interior node (t=m/1023, node=t*2047+1024+i), lda=K
template <int MODE>
__device__ __forceinline__ const __half* a_row(const __half* __restrict__ A,
                                               int gm, int K, int shift, int off_child)
{
    if (MODE == 0) return A + (size_t)gm * K;
    if (MODE == 1) {
        int t = gm >> shift, i = gm & ((1 << shift) - 1);
        return A + (size_t)(t * PER_TREE + off_child + 2 * i) * HID;
    }
    if (MODE == 2) {
        int t = gm >> shift, j = gm & ((1 << shift) - 1);
        return A + (size_t)(t * PER_TREE + off_child + j) * HID;
    }
    unsigned t = (unsigned)gm / 1023u;
    unsigned i = (unsigned)gm - t * 1023u;
    return A + (size_t)(t * 2047u + 1024u + i) * (size_t)K;
}

// ---- cp.async staging: 16B chunks, 4 per 64B row; swizzle chunk' = chunk ^ ((row>>1)&3).
template <int MODE>
__device__ __forceinline__ void stage_cp(uint32_t sA, uint32_t sB,
    const __half* __restrict__ A, const __half* __restrict__ B,
    int M, int K, int bm, int bn, int k0, int shift, int off_child, int tid)
{
#pragma unroll
    for (int q = 0; q < 2; q++) {      // A: 512 chunks, 2 per thread
        int id = q * 256 + tid;
        int r = id >> 2, cch = id & 3;
        int gm = bm + r;
        unsigned sz = 16u;
        if (gm >= M) { sz = 0u; gm = M - 1; }
        const __half* rowA = a_row<MODE>(A, gm, K, shift, off_child);
        uint32_t dst = sA + r * 64 + ((cch ^ ((r >> 1) & 3)) << 4);
        asm volatile("cp.async.cg.shared.global [%0], [%1], 16, %2;"
            :: "r"(dst), "l"(rowA + k0 + cch * 8), "r"(sz) : "memory");
    }
#pragma unroll
    for (int q = 0; q < 2; q++) {      // B: 512 chunks, 2 per thread
        int id = q * 256 + tid;
        int r = id >> 2, cch = id & 3;
        uint32_t dst = sB + r * 64 + ((cch ^ ((r >> 1) & 3)) << 4);
        asm volatile("cp.async.cg.shared.global [%0], [%1], 16;"
            :: "r"(dst), "l"(B + (size_t)(bn + r) * K + k0 + cch * 8) : "memory");
    }
}

// ---- Fragment loads for one k16 chunk (kc = 0 or 1) ----
__device__ __forceinline__ void load_frags(uint32_t (&af)[4][4], uint32_t (&bf)[4][2],
    uint32_t sAo, uint32_t sBo, int wm, int wn, int lane, int kc)
{
    const int arow = lane & 15;
    const int ca = kc * 2 + ((lane >> 4) & 1);
#pragma unroll
    for (int mt = 0; mt < 4; mt++) {
        int r = wm + mt * 16 + arow;
        ldsm4(af[mt][0], af[mt][1], af[mt][2], af[mt][3],
              sAo + r * 64 + ((ca ^ ((r >> 1) & 3)) << 4));
    }
    const int brow = (lane & 7) + ((lane >> 4) & 1) * 8;
    const int cb = kc * 2 + ((lane >> 3) & 1);
#pragma unroll
    for (int ng = 0; ng < 2; ng++) {
        int r = wn + ng * 16 + brow;
        uint32_t r0, r1, r2, r3;
        ldsm4(r0, r1, r2, r3, sBo + r * 64 + ((cb ^ ((r >> 1) & 3)) << 4));
        bf[ng * 2][0] = r0;     bf[ng * 2][1] = r1;
        bf[ng * 2 + 1][0] = r2; bf[ng * 2 + 1][1] = r3;
    }
}
__device__ __forceinline__ void mma_all(float (&acc)[4][4][4],
    const uint32_t (&af)[4][4], const uint32_t (&bf)[4][2])
{
#pragma unroll
    for (int mt = 0; mt < 4; mt++)
#pragma unroll
        for (int nt = 0; nt < 4; nt++)
            mma16(acc[mt][nt], af[mt][0], af[mt][1], af[mt][2], af[mt][3],
                  bf[nt][0], bf[nt][1]);
}

// ---------------- GEMM body (one CTA tile) ----------------
// MODE 0: C[gm] direct, +bias AddF
// MODE 1: C[gm] direct, +AddH = g_Xiou16[parent*IOUD + gn]
// MODE 2: C[gm] direct, no addend
// MODE 3: C scattered to interior node row, +bias AddF
template <int MODE>
__device__ __forceinline__ void gemm_body(
    const __half* __restrict__ A, const __half* __restrict__ B,
    __half* __restrict__ C, const float* __restrict__ AddF, const __half* __restrict__ AddH,
    int M, int Nd, int K, int shift, int off_parent, int off_child,
    int bm, int bn, uint32_t sb)
{
    const int tid = threadIdx.x, lane = tid & 31, wid = tid >> 5;
    const int wm = (wid & 1) * 64, wn = (wid >> 1) * 32;
    const int g = lane >> 2, tig = lane & 3;

    float acc[4][4][4];
#pragma unroll
    for (int mt = 0; mt < 4; mt++)
#pragma unroll
        for (int nt = 0; nt < 4; nt++)
#pragma unroll
            for (int r = 0; r < 4; r++) acc[mt][nt][r] = 0.f;

    const int NC = K >> 5;
    stage_cp<MODE>(sb, sb + A_STG, A, B, M, K, bm, bn, 0, shift, off_child, tid);
    asm volatile("cp.async.commit_group;" ::: "memory");
    stage_cp<MODE>(sb + STG, sb + STG + A_STG, A, B, M, K, bm, bn, BK, shift, off_child, tid);
    asm volatile("cp.async.commit_group;" ::: "memory");
    asm volatile("cp.async.wait_group 1;" ::: "memory");
    __syncthreads();

    for (int s = 0; s < NC; s++) {
        const uint32_t sAo = sb + (s % 3) * STG;
        const uint32_t sBo = sAo + A_STG;
        uint32_t af[4][4], bf[4][2];

        load_frags(af, bf, sAo, sBo, wm, wn, lane, 0);
        mma_all(acc, af, bf);

        if (s + 2 < NC) {
            const uint32_t so = sb + ((s + 2) % 3) * STG;
            stage_cp<MODE>(so, so + A_STG, A, B, M, K, bm, bn, (s + 2) * BK,
                           shift, off_child, tid);
            asm volatile("cp.async.commit_group;" ::: "memory");
        }

        load_frags(af, bf, sAo, sBo, wm, wn, lane, 1);
        mma_all(acc, af, bf);

        if (s + 1 < NC) {
            if (s + 2 < NC) { asm volatile("cp.async.wait_group 1;" ::: "memory"); }
            else            { asm volatile("cp.async.wait_group 0;" ::: "memory"); }
            __syncthreads();
        }
    }

    // ---- epilogue (fp16 C) ----
#pragma unroll
    for (int mt = 0; mt < 4; mt++) {
#pragma unroll
        for (int half_ = 0; half_ < 2; half_++) {
            int gm = bm + wm + mt * 16 + g + half_ * 8;
            if (gm >= M) continue;
            size_t crow, addb = 0;
            if (MODE == 3) {
                unsigned t = (unsigned)gm / 1023u;
                unsigned i = (unsigned)gm - t * 1023u;
                crow = (size_t)(t * 2047u + 1024u + i) * Nd;
            } else {
                crow = (size_t)gm * Nd;
            }
            if (MODE == 1) {
                int t = gm >> shift, ii = gm & ((1 << shift) - 1);
                addb = (size_t)(t * PER_TREE + off_parent + ii) * IOUD;
            }
#pragma unroll
            for (int nt = 0; nt < 4; nt++) {
                int gn = bn + wn + nt * 8 + 2 * tig;
                float vx = acc[mt][nt][half_ * 2 + 0];
                float vy = acc[mt][nt][half_ * 2 + 1];
                if (MODE == 0 || MODE == 3) { vx += AddF[gn]; vy += AddF[gn + 1]; }
                else if (MODE == 1) {
                    float2 a = __half22float2(*reinterpret_cast<const __half2*>(AddH + addb + gn));
                    vx += a.x; vy += a.y;
                }
                *reinterpret_cast<__half2*>(C + crow + gn) = __floats2half2_rn(vx, vy);
            }
        }
    }
}

// ---------------- Fused projection kernel: Xiou (MODE 0) + Xf (MODE 3) in one launch ----
// bid < Bp0: Xiou tile (12 N-tiles x 800 M-tiles), Nd=1536, all nodes
// else:      Xf tile   (4 N-tiles x 400 M-tiles),  Nd=512, interior scatter
__global__ void __launch_bounds__(256, 2) gemm_proj_k(
    const __half* __restrict__ feat, const __half* __restrict__ W,
    __half* __restrict__ Xiou, __half* __restrict__ Xf,
    const float* __restrict__ bc, int Bp0)
{
    __shared__ __align__(16) unsigned char smem[STAGES * STG];
    const uint32_t sb = (uint32_t)__cvta_generic_to_shared(smem);
    int bid = blockIdx.x;
    if (bid < Bp0) {
        int bxn = bid % 12, bym = bid / 12;
        gemm_body<0>(feat, W, Xiou, bc, nullptr,
                     NNODES, IOUD, FEAT, 0, 0, 0, bym * BM, bxn * BN, sb);
    } else {
        int b2 = bid - Bp0;
        int bxn = b2 % 4, bym = b2 / 4;
        gemm_body<3>(feat, W + (size_t)IOUD * FEAT, Xf, bc + IOUD, nullptr,
                     NINTER, HID, FEAT, 0, 0, 0, bym * BM, bxn * BN, sb);
    }
}

// ---------------- Fused per-level kernel: iou GEMM + fg GEMM in one launch ----------------
__global__ void __launch_bounds__(256, 2) gemm_level_k(
    const __half* __restrict__ h16,
    const __half* __restrict__ Uiou, const __half* __restrict__ Uf,
    __half* __restrict__ ioub, __half* __restrict__ fgb,
    const __half* __restrict__ Xiou,
    int P, int shift, int off_p, int off_c, int Biou)
{
    __shared__ __align__(16) unsigned char smem[STAGES * STG];
    const uint32_t sb = (uint32_t)__cvta_generic_to_shared(smem);
    int bid = blockIdx.x;
    if (bid < Biou) {
        int bxn = bid % 12, bym = bid / 12;
        gemm_body<1>(h16, Uiou, ioub, nullptr, Xiou,
                     P, IOUD, 1024, shift, off_p, off_c, bym * BM, bxn * BN, sb);
    } else {
        int b2 = bid - Biou;
        int bxn = b2 % 8, bym = b2 / 8;
        gemm_body<2>(h16, Uf, fgb, nullptr, nullptr,
                     2 * P, 1024, 512, shift + 1, 0, off_c, bym * BM, bxn * BN, sb);
    }
}

// ---------------- Conversion / packing ----------------
__global__ void f2h_kernel(const float* __restrict__ s, __half* __restrict__ d, int n2) {
    int i = blockIdx.x * blockDim.x + threadIdx.x;
    if (i >= n2) return;
    float2 v = reinterpret_cast<const float2*>(s)[i];
    reinterpret_cast<__half2*>(d)[i] = __floats2half2_rn(v.x, v.y);
}
__global__ void pack_W16(const float* __restrict__ Wiou, const float* __restrict__ Wf,
                         const float* __restrict__ biou, const float* __restrict__ bfp,
                         __half* __restrict__ W, float* __restrict__ bc) {
    int idx = blockIdx.x * blockDim.x + threadIdx.x;
    if (idx >= 2048 * FEAT) return;
    int j = idx >> 9, k = idx & 511;
    float v = (j < IOUD) ? Wiou[j * FEAT + k] : Wf[(j - IOUD) * FEAT + k];
    W[idx] = __float2half(v);
    if (k == 0) bc[j] = (j < IOUD) ? biou[j] : bfp[j - IOUD];
}
__global__ void pack_Uiou16(const float* __restrict__ Ul, const float* __restrict__ Ur,
                            __half* __restrict__ U) {
    int idx = blockIdx.x * blockDim.x + threadIdx.x;
    if (idx >= IOUD * 1024) return;
    int j = idx >> 10, k = idx & 1023;
    U[idx] = __float2half((k < 512) ? Ul[j * 512 + k] : Ur[j * 512 + (k - 512)]);
}
__global__ void pack_Uf16(const float* __restrict__ Ul, const float* __restrict__ Ur,
                          __half* __restrict__ U) {
    int idx = blockIdx.x * blockDim.x + threadIdx.x;
    if (idx >= 1024 * HID) return;
    U[idx] = __float2half((idx < 512 * 512) ? Ul[idx] : Ur[idx - 512 * 512]);
}

// ---------------- Leaf elementwise (2 elems/thread, half2) ----------------
__global__ void leaf_kernel(const __half* __restrict__ Xiou,
                            float* __restrict__ h, float* __restrict__ c,
                            __half* __restrict__ h16, int total)
{
    int idx = blockIdx.x * blockDim.x + threadIdx.x;   // NLEAVES * 256
    if (idx >= total) return;
    int leaf = idx >> 8, p = idx & 255;
    int hid = p * 2;
    int t = leaf >> 10, i = leaf & 1023;
    int node = t * PER_TREE + i;
    size_t base = (size_t)node * IOUD;
    float2 iv = __half22float2(*reinterpret_cast<const __half2*>(Xiou + base + hid));
    float2 ov = __half22float2(*reinterpret_cast<const __half2*>(Xiou + base + 512 + hid));
    float2 uv = __half22float2(*reinterpret_cast<const __half2*>(Xiou + base + 1024 + hid));
    float cnx = sigmoidf_(iv.x) * tanhf(uv.x);
    float cny = sigmoidf_(iv.y) * tanhf(uv.y);
    float hnx = sigmoidf_(ov.x) * tanhf(cnx);
    float hny = sigmoidf_(ov.y) * tanhf(cny);
    size_t ob = (size_t)node * HID + hid;
    *reinterpret_cast<float2*>(c + ob) = make_float2(cnx, cny);
    *reinterpret_cast<float2*>(h + ob) = make_float2(hnx, hny);
    *reinterpret_cast<__half2*>(h16 + ob) = __floats2half2_rn(hnx, hny);
}

// ---------------- Per-level combine (2 elems/thread) ----------------
__global__ void combine_kernel(const __half* __restrict__ iou, const __half* __restrict__ fg,
                               const __half* __restrict__ Xf,
                               float* __restrict__ h, float* __restrict__ c,
                               __half* __restrict__ h16,
                               int P, int shift, int off_parent, int off_child)
{
    int idx = blockIdx.x * blockDim.x + threadIdx.x;   // P * 256
    if (idx >= P * 256) return;
    int pid = idx >> 8, p = idx & 255;
    int hid = p * 2;
    int t = pid >> shift, i = pid & ((1 << shift) - 1);
    int node = t * PER_TREE + off_parent + i;
    int cl   = t * PER_TREE + off_child + 2 * i;

    size_t ib = (size_t)pid * IOUD;
    float2 iv = __half22float2(*reinterpret_cast<const __half2*>(iou + ib + hid));
    float2 ov = __half22float2(*reinterpret_cast<const __half2*>(iou + ib + 512 + hid));
    float2 uv = __half22float2(*reinterpret_cast<const __half2*>(iou + ib + 1024 + hid));
    float2 xf = __half22float2(*reinterpret_cast<const __half2*>(Xf + (size_t)node * HID + hid));

    size_t fL = (size_t)(2 * pid) * 1024;
    size_t fR = fL + 1024;
    float2 glL = __half22float2(*reinterpret_cast<const __half2*>(fg + fL + hid));
    float2 grL = __half22float2(*reinterpret_cast<const __half2*>(fg + fL + 512 + hid));
    float2 glR = __half22float2(*reinterpret_cast<const __half2*>(fg + fR + hid));
    float2 grR = __half22float2(*reinterpret_cast<const __half2*>(fg + fR + 512 + hid));
    float2 ccL = *reinterpret_cast<const float2*>(c + (size_t)cl * HID + hid);
    float2 ccR = *reinterpret_cast<const float2*>(c + (size_t)(cl + 1) * HID + hid);

    float fcx = (sigmoidf_(xf.x + glL.x) + sigmoidf_(xf.x + grL.x)) * ccL.x
              + (sigmoidf_(xf.x + glR.x) + sigmoidf_(xf.x + grR.x)) * ccR.x;
    float fcy = (sigmoidf_(xf.y + glL.y) + sigmoidf_(xf.y + grL.y)) * ccL.y
              + (sigmoidf_(xf.y + glR.y) + sigmoidf_(xf.y + grR.y)) * ccR.y;

    float cnx = sigmoidf_(iv.x) * tanhf(uv.x) + fcx;
    float cny = sigmoidf_(iv.y) * tanhf(uv.y) + fcy;
    float hnx = sigmoidf_(ov.x) * tanhf(cnx);
    float hny = sigmoidf_(ov.y) * tanhf(cny);
    size_t ob = (size_t)node * HID + hid;
    *reinterpret_cast<float2*>(c + ob) = make_float2(cnx, cny);
    *reinterpret_cast<float2*>(h + ob) = make_float2(hnx, hny);
    *reinterpret_cast<__half2*>(h16 + ob) = __floats2half2_rn(hnx, hny);
}

// ---------------- Launch ----------------
extern "C" void kernel_launch(void* const* d_in, const int* in_sizes, int n_in,
                              void* d_out, int out_size)
{
    const float* features = (const float*)d_in[0];
    const float* W_iou_w = (const float*)d_in[4];
    const float* W_iou_b = (const float*)d_in[5];
    const float* U_iou_l = (const float*)d_in[6];
    const float* U_iou_r = (const float*)d_in[7];
    const float* W_f_w   = (const float*)d_in[8];
    const float* W_f_b   = (const float*)d_in[9];
    const float* U_f_l   = (const float*)d_in[10];
    const float* U_f_r   = (const float*)d_in[11];

    float* h = (float*)d_out;
    float* c = h + (size_t)NNODES * HID;

    float *bcat;
    __half *xiou16, *xf16, *ioub, *fgb, *feat16, *h16, *w16, *uiou16, *uf16;
    cudaGetSymbolAddress((void**)&xiou16, g_Xiou16);
    cudaGetSymbolAddress((void**)&xf16,   g_Xf16);
    cudaGetSymbolAddress((void**)&ioub,   g_iou16);
    cudaGetSymbolAddress((void**)&fgb,    g_fg16);
    cudaGetSymbolAddress((void**)&bcat,   g_bcat);
    cudaGetSymbolAddress((void**)&feat16, g_feat16);
    cudaGetSymbolAddress((void**)&h16,    g_h16);
    cudaGetSymbolAddress((void**)&w16,    g_W16);
    cudaGetSymbolAddress((void**)&uiou16, g_Uiou16);
    cudaGetSymbolAddress((void**)&uf16,   g_Uf16);

    // One-time conversions/packing (fp32 -> fp16)
    {
        int n2 = NNODES * FEAT / 2;
        f2h_kernel<<<(n2 + 255) / 256, 256>>>(features, feat16, n2);
    }
    pack_W16   <<<(2048 * FEAT + 255) / 256, 256>>>(W_iou_w, W_f_w, W_iou_b, W_f_b, w16, bcat);
    pack_Uiou16<<<(IOUD * 1024 + 255) / 256, 256>>>(U_iou_l, U_iou_r, uiou16);
    pack_Uf16  <<<(1024 * HID + 255) / 256, 256>>>(U_f_l, U_f_r, uf16);

    // Fused projections: Xiou (all nodes, Nd=1536) + Xf (interior, Nd=512) in ONE launch
    {
        int Bp0 = 12 * ((NNODES + BM - 1) / BM);   // 9600
        int Bp3 = 4 * ((NINTER + BM - 1) / BM);    // 1600
        gemm_proj_k<<<Bp0 + Bp3, 256>>>(feat16, w16, xiou16, xf16, bcat, Bp0);
    }

    leaf_kernel<<<(NLEAVES * 256 + 255) / 256, 256>>>(xiou16, h, c, h16, NLEAVES * 256);

    for (int l = 1; l <= DEPTH; l++) {
        int n_l    = 1024 >> l;
        int P      = TREES * n_l;
        int shiftP = 10 - l;
        int off_p  = 2048 - (2048 >> l);
        int off_c  = 2048 - (2048 >> (l - 1));

        int Biou = 12 * ((P + BM - 1) / BM);
        int Bfg  = 8 * ((2 * P + BM - 1) / BM);
        gemm_level_k<<<Biou + Bfg, 256>>>(h16, uiou16, uf16, ioub, fgb, xiou16,
                                          P, shiftP, off_p, off_c, Biou);

        combine_kernel<<<(P * 256 + 255) / 256, 256>>>(ioub, fgb, xf16, h, c, h16,
                                                       P, shiftP, off_p, off_c);
    }
}

// round 16
// speedup vs baseline: 1.0566x; 1.0163x over previous
#include <cuda_runtime.h>
#include <cuda_fp16.h>
#include <math.h>
#include <stdint.h>

// ---------------- Static forest topology ----------------
#define TREES     50
#define DEPTH     10
#define PER_TREE  2047
#define NNODES    (TREES * PER_TREE)   // 102350
#define FEAT      512
#define HID       512
#define IOUD      1536
#define NLEAVES   (TREES * 1024)
#define NINTER    (TREES * 1023)       // 51150 interior nodes

// ---------------- Device scratch ----------------
__device__ __half g_Xiou16[(size_t)NNODES * IOUD];      // W_iou proj, all nodes
__device__ __half g_Xf16  [(size_t)NNODES * HID];       // W_f proj, interior rows only
__device__ __half g_iou16 [(size_t)(TREES * 512) * IOUD];
__device__ __half g_fg16  [(size_t)(TREES * 1024) * 1024];
__device__ float  g_bcat[2048];
__device__ __half g_feat16[(size_t)NNODES * FEAT];
__device__ __half g_h16   [(size_t)NNODES * HID];
__device__ __half g_W16   [(size_t)2048 * FEAT];        // [W_iou(1536) ; W_f(512)] rows
__device__ __half g_Uiou16[(size_t)IOUD * 1024];
__device__ __half g_Uf16  [(size_t)1024 * HID];

__device__ __forceinline__ float sigmoidf_(float x) { return 1.0f / (1.0f + expf(-x)); }

// ---- vector half helpers ----
__device__ __forceinline__ float4 ldh4(const __half* p) {
    uint2 u = *reinterpret_cast<const uint2*>(p);
    __half2 lo = *reinterpret_cast<__half2*>(&u.x);
    __half2 hi = *reinterpret_cast<__half2*>(&u.y);
    float2 flo = __half22float2(lo), fhi = __half22float2(hi);
    return make_float4(flo.x, flo.y, fhi.x, fhi.y);
}
__device__ __forceinline__ void sth4(__half* p, float4 v) {
    __half2 lo = __floats2half2_rn(v.x, v.y), hi = __floats2half2_rn(v.z, v.w);
    uint2 u;
    u.x = *reinterpret_cast<uint32_t*>(&lo);
    u.y = *reinterpret_cast<uint32_t*>(&hi);
    *reinterpret_cast<uint2*>(p) = u;
}

// ---------------- GEMM config (R12 proven optimum) ----------------
// CTA 128x128, BK=32 halves, 256 threads = 8 warps (2M x 4N), warp tile 64x32.
// 3-stage cp.async, 48KB static smem -> 2 CTAs/SM; <=128 regs via launch_bounds(256,2).
#define BM 128
#define BN 128
#define BK 32
#define A_STG 8192
#define B_STG 8192
#define STG   16384
#define STAGES 3                       // 49152 bytes static

__device__ __forceinline__ void mma16(float c[4], uint32_t a0, uint32_t a1, uint32_t a2,
                                      uint32_t a3, uint32_t b0, uint32_t b1) {
    asm volatile("mma.sync.aligned.m16n8k16.row.col.f32.f16.f16.f32 "
        "{%0,%1,%2,%3}, {%4,%5,%6,%7}, {%8,%9}, {%0,%1,%2,%3};"
        : "+f"(c[0]), "+f"(c[1]), "+f"(c[2]), "+f"(c[3])
        : "r"(a0), "r"(a1), "r"(a2), "r"(a3), "r"(b0), "r"(b1));
}
__device__ __forceinline__ void ldsm4(uint32_t& r0, uint32_t& r1, uint32_t& r2, uint32_t& r3,
                                      uint32_t a) {
    asm volatile("ldmatrix.sync.aligned.m8n8.x4.shared.b16 {%0,%1,%2,%3}, [%4];"
        : "=r"(r0), "=r"(r1), "=r"(r2), "=r"(r3) : "r"(a));
}

// ---- A-row gather per MODE:
// MODE 0: direct (lda=K)
// MODE 1: row m -> h16 of LEFT child (1024 contiguous halves span L+R child)
// MODE 2: row m -> h16 of child node (512 halves)
// MODE 3: row m -> interior node (t=m/1023, node=t*2047+1024+i), lda=K
template <int MODE>
__device__ __forceinline__ const __half* a_row(const __half* __restrict__ A,
                                               int gm, int K, int shift, int off_child)
{
    if (MODE == 0) return A + (size_t)gm * K;
    if (MODE == 1) {
        int t = gm >> shift, i = gm & ((1 << shift) - 1);
        return A + (size_t)(t * PER_TREE + off_child + 2 * i) * HID;
    }
    if (MODE == 2) {
        int t = gm >> shift, j = gm & ((1 << shift) - 1);
        return A + (size_t)(t * PER_TREE + off_child + j) * HID;
    }
    unsigned t = (unsigned)gm / 1023u;
    unsigned i = (unsigned)gm - t * 1023u;
    return A + (size_t)(t * 2047u + 1024u + i) * (size_t)K;
}

// ---- cp.async staging: 16B chunks, 4 per 64B row; swizzle chunk' = chunk ^ ((row>>1)&3).
template <int MODE>
__device__ __forceinline__ void stage_cp(uint32_t sA, uint32_t sB,
    const __half* __restrict__ A, const __half* __restrict__ B,
    int M, int K, int bm, int bn, int k0, int shift, int off_child, int tid)
{
#pragma unroll
    for (int q = 0; q < 2; q++) {      // A: 512 chunks, 2 per thread
        int id = q * 256 + tid;
        int r = id >> 2, cch = id & 3;
        int gm = bm + r;
        unsigned sz = 16u;
        if (gm >= M) { sz = 0u; gm = M - 1; }
        const __half* rowA = a_row<MODE>(A, gm, K, shift, off_child);
        uint32_t dst = sA + r * 64 + ((cch ^ ((r >> 1) & 3)) << 4);
        asm volatile("cp.async.cg.shared.global [%0], [%1], 16, %2;"
            :: "r"(dst), "l"(rowA + k0 + cch * 8), "r"(sz) : "memory");
    }
#pragma unroll
    for (int q = 0; q < 2; q++) {      // B: 512 chunks, 2 per thread
        int id = q * 256 + tid;
        int r = id >> 2, cch = id & 3;
        uint32_t dst = sB + r * 64 + ((cch ^ ((r >> 1) & 3)) << 4);
        asm volatile("cp.async.cg.shared.global [%0], [%1], 16;"
            :: "r"(dst), "l"(B + (size_t)(bn + r) * K + k0 + cch * 8) : "memory");
    }
}

// ---- Fragment loads for one k16 chunk (kc = 0 or 1) ----
__device__ __forceinline__ void load_frags(uint32_t (&af)[4][4], uint32_t (&bf)[4][2],
    uint32_t sAo, uint32_t sBo, int wm, int wn, int lane, int kc)
{
    const int arow = lane & 15;
    const int ca = kc * 2 + ((lane >> 4) & 1);
#pragma unroll
    for (int mt = 0; mt < 4; mt++) {
        int r = wm + mt * 16 + arow;
        ldsm4(af[mt][0], af[mt][1], af[mt][2], af[mt][3],
              sAo + r * 64 + ((ca ^ ((r >> 1) & 3)) << 4));
    }
    const int brow = (lane & 7) + ((lane >> 4) & 1) * 8;
    const int cb = kc * 2 + ((lane >> 3) & 1);
#pragma unroll
    for (int ng = 0; ng < 2; ng++) {
        int r = wn + ng * 16 + brow;
        uint32_t r0, r1, r2, r3;
        ldsm4(r0, r1, r2, r3, sBo + r * 64 + ((cb ^ ((r >> 1) & 3)) << 4));
        bf[ng * 2][0] = r0;     bf[ng * 2][1] = r1;
        bf[ng * 2 + 1][0] = r2; bf[ng * 2 + 1][1] = r3;
    }
}
__device__ __forceinline__ void mma_all(float (&acc)[4][4][4],
    const uint32_t (&af)[4][4], const uint32_t (&bf)[4][2])
{
#pragma unroll
    for (int mt = 0; mt < 4; mt++)
#pragma unroll
        for (int nt = 0; nt < 4; nt++)
            mma16(acc[mt][nt], af[mt][0], af[mt][1], af[mt][2], af[mt][3],
                  bf[nt][0], bf[nt][1]);
}

// ---------------- GEMM body (one CTA tile) ----------------
// MODE 0: C[gm] direct, +bias AddF
// MODE 1: C[gm] direct, +AddH = g_Xiou16[parent*IOUD + gn]
// MODE 2: C[gm] direct, no addend
// MODE 3: C scattered to interior node row, +bias AddF
template <int MODE>
__device__ __forceinline__ void gemm_body(
    const __half* __restrict__ A, const __half* __restrict__ B,
    __half* __restrict__ C, const float* __restrict__ AddF, const __half* __restrict__ AddH,
    int M, int Nd, int K, int shift, int off_parent, int off_child,
    int bm, int bn, uint32_t sb)
{
    const int tid = threadIdx.x, lane = tid & 31, wid = tid >> 5;
    const int wm = (wid & 1) * 64, wn = (wid >> 1) * 32;
    const int g = lane >> 2, tig = lane & 3;

    float acc[4][4][4];
#pragma unroll
    for (int mt = 0; mt < 4; mt++)
#pragma unroll
        for (int nt = 0; nt < 4; nt++)
#pragma unroll
            for (int r = 0; r < 4; r++) acc[mt][nt][r] = 0.f;

    const int NC = K >> 5;
    stage_cp<MODE>(sb, sb + A_STG, A, B, M, K, bm, bn, 0, shift, off_child, tid);
    asm volatile("cp.async.commit_group;" ::: "memory");
    stage_cp<MODE>(sb + STG, sb + STG + A_STG, A, B, M, K, bm, bn, BK, shift, off_child, tid);
    asm volatile("cp.async.commit_group;" ::: "memory");
    asm volatile("cp.async.wait_group 1;" ::: "memory");
    __syncthreads();

    for (int s = 0; s < NC; s++) {
        const uint32_t sAo = sb + (s % 3) * STG;
        const uint32_t sBo = sAo + A_STG;
        uint32_t af[4][4], bf[4][2];

        load_frags(af, bf, sAo, sBo, wm, wn, lane, 0);
        mma_all(acc, af, bf);

        if (s + 2 < NC) {
            const uint32_t so = sb + ((s + 2) % 3) * STG;
            stage_cp<MODE>(so, so + A_STG, A, B, M, K, bm, bn, (s + 2) * BK,
                           shift, off_child, tid);
            asm volatile("cp.async.commit_group;" ::: "memory");
        }

        load_frags(af, bf, sAo, sBo, wm, wn, lane, 1);
        mma_all(acc, af, bf);

        if (s + 1 < NC) {
            if (s + 2 < NC) { asm volatile("cp.async.wait_group 1;" ::: "memory"); }
            else            { asm volatile("cp.async.wait_group 0;" ::: "memory"); }
            __syncthreads();
        }
    }

    // ---- epilogue (fp16 C) ----
#pragma unroll
    for (int mt = 0; mt < 4; mt++) {
#pragma unroll
        for (int half_ = 0; half_ < 2; half_++) {
            int gm = bm + wm + mt * 16 + g + half_ * 8;
            if (gm >= M) continue;
            size_t crow, addb = 0;
            if (MODE == 3) {
                unsigned t = (unsigned)gm / 1023u;
                unsigned i = (unsigned)gm - t * 1023u;
                crow = (size_t)(t * 2047u + 1024u + i) * Nd;
            } else {
                crow = (size_t)gm * Nd;
            }
            if (MODE == 1) {
                int t = gm >> shift, ii = gm & ((1 << shift) - 1);
                addb = (size_t)(t * PER_TREE + off_parent + ii) * IOUD;
            }
#pragma unroll
            for (int nt = 0; nt < 4; nt++) {
                int gn = bn + wn + nt * 8 + 2 * tig;
                float vx = acc[mt][nt][half_ * 2 + 0];
                float vy = acc[mt][nt][half_ * 2 + 1];
                if (MODE == 0 || MODE == 3) { vx += AddF[gn]; vy += AddF[gn + 1]; }
                else if (MODE == 1) {
                    float2 a = __half22float2(*reinterpret_cast<const __half2*>(AddH + addb + gn));
                    vx += a.x; vy += a.y;
                }
                *reinterpret_cast<__half2*>(C + crow + gn) = __floats2half2_rn(vx, vy);
            }
        }
    }
}

// ---------------- Fused projection kernel: Xiou (MODE 0) + Xf (MODE 3) in one launch ----
__global__ void __launch_bounds__(256, 2) gemm_proj_k(
    const __half* __restrict__ feat, const __half* __restrict__ W,
    __half* __restrict__ Xiou, __half* __restrict__ Xf,
    const float* __restrict__ bc, int Bp0)
{
    __shared__ __align__(16) unsigned char smem[STAGES * STG];
    const uint32_t sb = (uint32_t)__cvta_generic_to_shared(smem);
    int bid = blockIdx.x;
    if (bid < Bp0) {
        int bxn = bid % 12, bym = bid / 12;
        gemm_body<0>(feat, W, Xiou, bc, nullptr,
                     NNODES, IOUD, FEAT, 0, 0, 0, bym * BM, bxn * BN, sb);
    } else {
        int b2 = bid - Bp0;
        int bxn = b2 % 4, bym = b2 / 4;
        gemm_body<3>(feat, W + (size_t)IOUD * FEAT, Xf, bc + IOUD, nullptr,
                     NINTER, HID, FEAT, 0, 0, 0, bym * BM, bxn * BN, sb);
    }
}

// ---------------- Fused per-level kernel: iou GEMM + fg GEMM in one launch ----------------
__global__ void __launch_bounds__(256, 2) gemm_level_k(
    const __half* __restrict__ h16,
    const __half* __restrict__ Uiou, const __half* __restrict__ Uf,
    __half* __restrict__ ioub, __half* __restrict__ fgb,
    const __half* __restrict__ Xiou,
    int P, int shift, int off_p, int off_c, int Biou)
{
    __shared__ __align__(16) unsigned char smem[STAGES * STG];
    const uint32_t sb = (uint32_t)__cvta_generic_to_shared(smem);
    int bid = blockIdx.x;
    if (bid < Biou) {
        int bxn = bid % 12, bym = bid / 12;
        gemm_body<1>(h16, Uiou, ioub, nullptr, Xiou,
                     P, IOUD, 1024, shift, off_p, off_c, bym * BM, bxn * BN, sb);
    } else {
        int b2 = bid - Biou;
        int bxn = b2 % 8, bym = b2 / 8;
        gemm_body<2>(h16, Uf, fgb, nullptr, nullptr,
                     2 * P, 1024, 512, shift + 1, 0, off_c, bym * BM, bxn * BN, sb);
    }
}

// ---------------- Fused setup kernel: f2h(features) + pack W/Uiou/Uf ----------------
#define N4     (NNODES * FEAT / 4)             // 13100800 float4's
#define B_F2H  (N4 / 256)                      // 51175 (exact)
#define B_W    (2048 * FEAT / 256)             // 4096
#define B_UI   (IOUD * 1024 / 256)             // 6144
#define B_UF   (1024 * HID / 256)              // 2048
#define B_SETUP (B_F2H + B_W + B_UI + B_UF)

__global__ void setup_k(const float* __restrict__ feat,
                        const float* __restrict__ Wiou, const float* __restrict__ Wf,
                        const float* __restrict__ biou, const float* __restrict__ bfp,
                        const float* __restrict__ Uil,  const float* __restrict__ Uir,
                        const float* __restrict__ Ufl,  const float* __restrict__ Ufr,
                        __half* __restrict__ feat16, __half* __restrict__ W,
                        float* __restrict__ bc,
                        __half* __restrict__ Ui, __half* __restrict__ Uf_)
{
    int bid = blockIdx.x;
    if (bid < B_F2H) {
        int i = bid * 256 + threadIdx.x;       // < N4
        float4 v = reinterpret_cast<const float4*>(feat)[i];
        sth4(feat16 + (size_t)i * 4, v);
    } else if (bid < B_F2H + B_W) {
        int idx = (bid - B_F2H) * 256 + threadIdx.x;   // 2048*512
        int j = idx >> 9, k = idx & 511;
        float v = (j < IOUD) ? Wiou[j * FEAT + k] : Wf[(j - IOUD) * FEAT + k];
        W[idx] = __float2half(v);
        if (k == 0) bc[j] = (j < IOUD) ? biou[j] : bfp[j - IOUD];
    } else if (bid < B_F2H + B_W + B_UI) {
        int idx = (bid - B_F2H - B_W) * 256 + threadIdx.x;  // 1536*1024
        int j = idx >> 10, k = idx & 1023;
        Ui[idx] = __float2half((k < 512) ? Uil[j * 512 + k] : Uir[j * 512 + (k - 512)]);
    } else {
        int idx = (bid - B_F2H - B_W - B_UI) * 256 + threadIdx.x;  // 1024*512
        Uf_[idx] = __float2half((idx < 512 * 512) ? Ufl[idx] : Ufr[idx - 512 * 512]);
    }
}

// ---------------- Leaf elementwise (4 elems/thread) ----------------
__global__ void leaf_kernel(const __half* __restrict__ Xiou,
                            float* __restrict__ h, float* __restrict__ c,
                            __half* __restrict__ h16, int total)
{
    int idx = blockIdx.x * blockDim.x + threadIdx.x;   // NLEAVES * 128
    if (idx >= total) return;
    int leaf = idx >> 7, p = idx & 127;
    int hid = p * 4;
    int t = leaf >> 10, i = leaf & 1023;
    int node = t * PER_TREE + i;
    size_t base = (size_t)node * IOUD;
    float4 iv = ldh4(Xiou + base + hid);
    float4 ov = ldh4(Xiou + base + 512 + hid);
    float4 uv = ldh4(Xiou + base + 1024 + hid);
    float4 cn, hn;
    cn.x = sigmoidf_(iv.x) * tanhf(uv.x); hn.x = sigmoidf_(ov.x) * tanhf(cn.x);
    cn.y = sigmoidf_(iv.y) * tanhf(uv.y); hn.y = sigmoidf_(ov.y) * tanhf(cn.y);
    cn.z = sigmoidf_(iv.z) * tanhf(uv.z); hn.z = sigmoidf_(ov.z) * tanhf(cn.z);
    cn.w = sigmoidf_(iv.w) * tanhf(uv.w); hn.w = sigmoidf_(ov.w) * tanhf(cn.w);
    size_t ob = (size_t)node * HID + hid;
    *reinterpret_cast<float4*>(c + ob) = cn;
    *reinterpret_cast<float4*>(h + ob) = hn;
    sth4(h16 + ob, hn);
}

// ---------------- Per-level combine (4 elems/thread) ----------------
__global__ void combine_kernel(const __half* __restrict__ iou, const __half* __restrict__ fg,
                               const __half* __restrict__ Xf,
                               float* __restrict__ h, float* __restrict__ c,
                               __half* __restrict__ h16,
                               int P, int shift, int off_parent, int off_child)
{
    int idx = blockIdx.x * blockDim.x + threadIdx.x;   // P * 128
    if (idx >= P * 128) return;
    int pid = idx >> 7, p = idx & 127;
    int hid = p * 4;
    int t = pid >> shift, i = pid & ((1 << shift) - 1);
    int node = t * PER_TREE + off_parent + i;
    int cl   = t * PER_TREE + off_child + 2 * i;

    size_t ib = (size_t)pid * IOUD;
    float4 iv = ldh4(iou + ib + hid);
    float4 ov = ldh4(iou + ib + 512 + hid);
    float4 uv = ldh4(iou + ib + 1024 + hid);
    float4 xf = ldh4(Xf + (size_t)node * HID + hid);

    size_t fL = (size_t)(2 * pid) * 1024;
    size_t fR = fL + 1024;
    float4 glL = ldh4(fg + fL + hid);
    float4 grL = ldh4(fg + fL + 512 + hid);
    float4 glR = ldh4(fg + fR + hid);
    float4 grR = ldh4(fg + fR + 512 + hid);
    float4 ccL = *reinterpret_cast<const float4*>(c + (size_t)cl * HID + hid);
    float4 ccR = *reinterpret_cast<const float4*>(c + (size_t)(cl + 1) * HID + hid);

    float4 cn, hn;
    {
        float fc = (sigmoidf_(xf.x + glL.x) + sigmoidf_(xf.x + grL.x)) * ccL.x
                 + (sigmoidf_(xf.x + glR.x) + sigmoidf_(xf.x + grR.x)) * ccR.x;
        cn.x = sigmoidf_(iv.x) * tanhf(uv.x) + fc;
        hn.x = sigmoidf_(ov.x) * tanhf(cn.x);
    }
    {
        float fc = (sigmoidf_(xf.y + glL.y) + sigmoidf_(xf.y + grL.y)) * ccL.y
                 + (sigmoidf_(xf.y + glR.y) + sigmoidf_(xf.y + grR.y)) * ccR.y;
        cn.y = sigmoidf_(iv.y) * tanhf(uv.y) + fc;
        hn.y = sigmoidf_(ov.y) * tanhf(cn.y);
    }
    {
        float fc = (sigmoidf_(xf.z + glL.z) + sigmoidf_(xf.z + grL.z)) * ccL.z
                 + (sigmoidf_(xf.z + glR.z) + sigmoidf_(xf.z + grR.z)) * ccR.z;
        cn.z = sigmoidf_(iv.z) * tanhf(uv.z) + fc;
        hn.z = sigmoidf_(ov.z) * tanhf(cn.z);
    }
    {
        float fc = (sigmoidf_(xf.w + glL.w) + sigmoidf_(xf.w + grL.w)) * ccL.w
                 + (sigmoidf_(xf.w + glR.w) + sigmoidf_(xf.w + grR.w)) * ccR.w;
        cn.w = sigmoidf_(iv.w) * tanhf(uv.w) + fc;
        hn.w = sigmoidf_(ov.w) * tanhf(cn.w);
    }
    size_t ob = (size_t)node * HID + hid;
    *reinterpret_cast<float4*>(c + ob) = cn;
    *reinterpret_cast<float4*>(h + ob) = hn;
    sth4(h16 + ob, hn);
}

// ---------------- Launch ----------------
extern "C" void kernel_launch(void* const* d_in, const int* in_sizes, int n_in,
                              void* d_out, int out_size)
{
    const float* features = (const float*)d_in[0];
    const float* W_iou_w = (const float*)d_in[4];
    const float* W_iou_b = (const float*)d_in[5];
    const float* U_iou_l = (const float*)d_in[6];
    const float* U_iou_r = (const float*)d_in[7];
    const float* W_f_w   = (const float*)d_in[8];
    const float* W_f_b   = (const float*)d_in[9];
    const float* U_f_l   = (const float*)d_in[10];
    const float* U_f_r   = (const float*)d_in[11];

    float* h = (float*)d_out;
    float* c = h + (size_t)NNODES * HID;

    float *bcat;
    __half *xiou16, *xf16, *ioub, *fgb, *feat16, *h16, *w16, *uiou16, *uf16;
    cudaGetSymbolAddress((void**)&xiou16, g_Xiou16);
    cudaGetSymbolAddress((void**)&xf16,   g_Xf16);
    cudaGetSymbolAddress((void**)&ioub,   g_iou16);
    cudaGetSymbolAddress((void**)&fgb,    g_fg16);
    cudaGetSymbolAddress((void**)&bcat,   g_bcat);
    cudaGetSymbolAddress((void**)&feat16, g_feat16);
    cudaGetSymbolAddress((void**)&h16,    g_h16);
    cudaGetSymbolAddress((void**)&w16,    g_W16);
    cudaGetSymbolAddress((void**)&uiou16, g_Uiou16);
    cudaGetSymbolAddress((void**)&uf16,   g_Uf16);

    // One fused setup launch: features f2h + all weight packing
    setup_k<<<B_SETUP, 256>>>(features, W_iou_w, W_f_w, W_iou_b, W_f_b,
                              U_iou_l, U_iou_r, U_f_l, U_f_r,
                              feat16, w16, bcat, uiou16, uf16);

    // Fused projections: Xiou (all nodes, Nd=1536) + Xf (interior, Nd=512) in ONE launch
    {
        int Bp0 = 12 * ((NNODES + BM - 1) / BM);   // 9600
        int Bp3 = 4 * ((NINTER + BM - 1) / BM);    // 1600
        gemm_proj_k<<<Bp0 + Bp3, 256>>>(feat16, w16, xiou16, xf16, bcat, Bp0);
    }

    leaf_kernel<<<(NLEAVES * 128 + 255) / 256, 256>>>(xiou16, h, c, h16, NLEAVES * 128);

    for (int l = 1; l <= DEPTH; l++) {
        int n_l    = 1024 >> l;
        int P      = TREES * n_l;
        int shiftP = 10 - l;
        int off_p  = 2048 - (2048 >> l);
        int off_c  = 2048 - (2048 >> (l - 1));

        int Biou = 12 * ((P + BM - 1) / BM);
        int Bfg  = 8 * ((2 * P + BM - 1) / BM);
        gemm_level_k<<<Biou + Bfg, 256>>>(h16, uiou16, uf16, ioub, fgb, xiou16,
                                          P, shiftP, off_p, off_c, Biou);

        combine_kernel<<<(P * 128 + 255) / 256, 256>>>(ioub, fgb, xf16, h, c, h16,
                                                       P, shiftP, off_p, off_c);
    }
}